// round 5
// baseline (speedup 1.0000x reference)
#include <cuda_runtime.h>
#include <cuda_bf16.h>
#include <math.h>

#define B_ 2
#define S_ 4096
#define D_ 512
#define H_ 8
#define DK_ 64
#define MROWS (B_ * S_)   // 8192

// ---------------- scratch (no allocations allowed) ----------------
__device__ float g_Q[MROWS * D_];
__device__ float g_K[MROWS * D_];   // compacted valid-key rows per batch
__device__ float g_V[MROWS * D_];   // compacted valid-key rows per batch
__device__ float g_AO[MROWS * D_];
__device__ int   g_idx[MROWS];      // per-batch local indices of valid keys
__device__ int   g_nvalid[B_];

// ---------------- helpers ----------------
__device__ __forceinline__ unsigned f2tf32(float f) {
    unsigned u;
    asm("cvt.rna.tf32.f32 %0, %1;" : "=r"(u) : "f"(f));
    return u;
}

__device__ __forceinline__ float ex2f(float x) {
    float y;
    asm("ex2.approx.ftz.f32 %0, %1;" : "=f"(y) : "f"(x));
    return y;
}

__device__ __forceinline__ void mma_tf32(float* c,
                                         unsigned a0, unsigned a1, unsigned a2, unsigned a3,
                                         unsigned b0, unsigned b1) {
    asm volatile(
        "mma.sync.aligned.m16n8k8.row.col.f32.tf32.tf32.f32 "
        "{%0,%1,%2,%3},{%4,%5,%6,%7},{%8,%9},{%0,%1,%2,%3};"
        : "+f"(c[0]), "+f"(c[1]), "+f"(c[2]), "+f"(c[3])
        : "r"(a0), "r"(a1), "r"(a2), "r"(a3), "r"(b0), "r"(b1));
}

// swizzles: keep 4-aligned blocks intact (XOR only bits >=2)
#define SW1(r, c) ((c) ^ (((r) & 7) << 2))   // for Q/P/K and GEMM tiles
#define SW2(r, c) ((c) ^ (((r) & 3) << 3))   // for V tile

// ---------------- mask compaction (deterministic prefix scan) ----------------
__global__ void compact_mask_kernel(const int* __restrict__ mask) {
    const int b = blockIdx.x;
    const int tid = threadIdx.x;        // 1024 threads, 4 elements each
    const int lane = tid & 31, wid = tid >> 5;
    __shared__ int wsum[32];
    const int* mb = mask + b * S_;
    const int base = tid * 4;
    int m0 = mb[base] != 0, m1 = mb[base + 1] != 0;
    int m2 = mb[base + 2] != 0, m3 = mb[base + 3] != 0;
    int c = m0 + m1 + m2 + m3;
    int x = c;
#pragma unroll
    for (int off = 1; off < 32; off <<= 1) {
        int y = __shfl_up_sync(0xffffffffu, x, off);
        if (lane >= off) x += y;
    }
    if (lane == 31) wsum[wid] = x;
    __syncthreads();
    if (wid == 0) {
        int v = wsum[lane];
#pragma unroll
        for (int off = 1; off < 32; off <<= 1) {
            int y = __shfl_up_sync(0xffffffffu, v, off);
            if (lane >= off) v += y;
        }
        wsum[lane] = v;
    }
    __syncthreads();
    int offset = x - c + (wid ? wsum[wid - 1] : 0);
    int* oi = g_idx + b * S_;
    if (m0) oi[offset++] = base;
    if (m1) oi[offset++] = base + 1;
    if (m2) oi[offset++] = base + 2;
    if (m3) oi[offset++] = base + 3;
    if (tid == 1023) g_nvalid[b] = wsum[31];
}

// ---------------- GEMM: C[M,512] = gather(A)[M,512] @ W[512,512]^T ----------------
// 128x128 block tile, 256 threads (8 warps, 4x2), warp tile 32x64, BK=32.
// Swizzled smem: stride 32 uints, col ^ ((row&7)<<2) -> conflict-free frag loads.
__device__ __forceinline__ void gemm_tile_mma(const float* __restrict__ A,
                                              const float* __restrict__ W,
                                              float* __restrict__ C,
                                              const int* __restrict__ rowsrc,
                                              int m0, int n0) {
    __shared__ unsigned As[128 * 32];
    __shared__ unsigned Ws[128 * 32];

    const int tid = threadIdx.x;
    const int lane = tid & 31;
    const int warp = tid >> 5;
    const int qlane = lane >> 2;   // 0..7
    const int klane = lane & 3;    // 0..3
    const int wm = (warp & 3) * 32;
    const int wn = (warp >> 2) * 64;

    float acc[2][8][4] = {};

    for (int kt = 0; kt < D_; kt += 32) {
        __syncthreads();
#pragma unroll
        for (int i = 0; i < 4; i++) {
            int idx = tid + i * 256;
            int r = idx >> 3, c4 = idx & 7;
            float4 av = *(const float4*)&A[rowsrc[r] * D_ + kt + c4 * 4];
            float4 wv = *(const float4*)&W[(n0 + r) * D_ + kt + c4 * 4];
            uint4 at = make_uint4(f2tf32(av.x), f2tf32(av.y), f2tf32(av.z), f2tf32(av.w));
            uint4 wt = make_uint4(f2tf32(wv.x), f2tf32(wv.y), f2tf32(wv.z), f2tf32(wv.w));
            *(uint4*)&As[r * 32 + SW1(r, c4 * 4)] = at;
            *(uint4*)&Ws[r * 32 + SW1(r, c4 * 4)] = wt;
        }
        __syncthreads();

#pragma unroll
        for (int ks = 0; ks < 4; ks++) {
            const int off = (ks * 8 + klane) ^ (qlane << 2);
            const int off4 = off ^ 4;
            unsigned a[2][4];
#pragma unroll
            for (int mt = 0; mt < 2; mt++) {
                int row = wm + mt * 16 + qlane;   // row&7 == qlane
                a[mt][0] = As[row * 32 + off];
                a[mt][1] = As[(row + 8) * 32 + off];
                a[mt][2] = As[row * 32 + off4];
                a[mt][3] = As[(row + 8) * 32 + off4];
            }
#pragma unroll
            for (int nt = 0; nt < 8; nt++) {
                int brow = wn + nt * 8 + qlane;   // row&7 == qlane
                unsigned b0 = Ws[brow * 32 + off];
                unsigned b1 = Ws[brow * 32 + off4];
#pragma unroll
                for (int mt = 0; mt < 2; mt++)
                    mma_tf32(acc[mt][nt], a[mt][0], a[mt][1], a[mt][2], a[mt][3], b0, b1);
            }
        }
    }

#pragma unroll
    for (int mt = 0; mt < 2; mt++) {
#pragma unroll
        for (int nt = 0; nt < 8; nt++) {
            int r0 = m0 + wm + mt * 16 + qlane;
            int c = n0 + wn + nt * 8 + 2 * klane;
            *(float2*)&C[r0 * D_ + c] = make_float2(acc[mt][nt][0], acc[mt][nt][1]);
            *(float2*)&C[(r0 + 8) * D_ + c] = make_float2(acc[mt][nt][2], acc[mt][nt][3]);
        }
    }
}

__global__ __launch_bounds__(256) void proj_qkv_kernel(const float* __restrict__ q,
                                                       const float* __restrict__ k,
                                                       const float* __restrict__ v,
                                                       const float* __restrict__ wq,
                                                       const float* __restrict__ wk,
                                                       const float* __restrict__ wv) {
    const int z = blockIdx.z;
    const int m0 = blockIdx.x * 128;
    const int n0 = blockIdx.y * 128;
    const int bb = m0 >> 12;          // batch (4096 rows per batch)
    const int tid = threadIdx.x;

    __shared__ int rowsrc[128];
    if (z == 0) {
        if (tid < 128) rowsrc[tid] = m0 + tid;
    } else {
        int nv = g_nvalid[bb];
        if ((m0 & (S_ - 1)) >= nv) return;   // whole tile beyond valid keys
        if (tid < 128) {
            int gr = m0 + tid;
            int li = gr & (S_ - 1);
            rowsrc[tid] = bb * S_ + ((li < nv) ? g_idx[bb * S_ + li] : 0);
        }
    }
    __syncthreads();

    const float* A = (z == 0) ? q : (z == 1) ? k : v;
    const float* W = (z == 0) ? wq : (z == 1) ? wk : wv;
    float* C = (z == 0) ? g_Q : (z == 1) ? g_K : g_V;
    gemm_tile_mma(A, W, C, rowsrc, m0, n0);
}

__global__ __launch_bounds__(256) void proj_out_kernel(const float* __restrict__ wo,
                                                       float* __restrict__ out) {
    const int m0 = blockIdx.x * 128;
    const int n0 = blockIdx.y * 128;
    __shared__ int rowsrc[128];
    if (threadIdx.x < 128) rowsrc[threadIdx.x] = m0 + threadIdx.x;
    __syncthreads();
    gemm_tile_mma(g_AO, wo, out, rowsrc, m0, n0);
}

// ---------------- Flash attention over compacted K/V (tf32 MMA) ----------------
// grid: (S/128, B*H), 256 threads (8 warps), each warp owns 16 q-rows.
// Q fragments live in registers (loaded once). Ps overlays Qs. Swizzled smem:
//   QsPs[128*64] (Q staging, then P), Ks[64*64], Vs[64*64]  -> 64 KB total.
#define OFF_K  (128 * 64)             // 8192
#define OFF_V  (OFF_K + 64 * 64)      // 12288
#define FSM_U  (OFF_V + 64 * 64)      // 16384
#define FSM_BYTES (FSM_U * 4)         // 65536

// log2(e) / sqrt(64)
#define QSCALE 0.1803368801111204f

__global__ __launch_bounds__(256) void flash_attn_kernel() {
    extern __shared__ unsigned smu[];
    unsigned* QsPs = smu;
    unsigned* Ks = smu + OFF_K;
    unsigned* Vs = smu + OFF_V;

    const int tid = threadIdx.x;
    const int lane = tid & 31;
    const int warp = tid >> 5;
    const int qlane = lane >> 2;
    const int klane = lane & 3;
    const int bh = blockIdx.y;
    const int b = bh >> 3;
    const int h = bh & 7;
    const int qm0 = blockIdx.x * 128;
    const int qr = warp * 16 + qlane;   // row within tile (and qr+8); qr&7 == qlane
    const int nv = g_nvalid[b];

    // stage Q tile (128 x 64), pre-scaled, swizzled
    const float* Qb = g_Q + (b * S_ + qm0) * D_ + h * DK_;
#pragma unroll
    for (int i = 0; i < 8; i++) {
        int idx = tid + i * 256;
        int r = idx >> 4, c4 = idx & 15;
        float4 qv = *(const float4*)&Qb[r * D_ + c4 * 4];
        uint4 qt = make_uint4(f2tf32(qv.x * QSCALE), f2tf32(qv.y * QSCALE),
                              f2tf32(qv.z * QSCALE), f2tf32(qv.w * QSCALE));
        *(uint4*)&QsPs[r * 64 + SW1(r, c4 * 4)] = qt;
    }
    __syncthreads();

    // extract Q fragments into registers (conflict-free)
    unsigned qf[8][4];
#pragma unroll
    for (int ks = 0; ks < 8; ks++) {
        int off = (ks * 8 + klane) ^ (qlane << 2);
        int off4 = off ^ 4;
        qf[ks][0] = QsPs[qr * 64 + off];
        qf[ks][1] = QsPs[(qr + 8) * 64 + off];
        qf[ks][2] = QsPs[qr * 64 + off4];
        qf[ks][3] = QsPs[(qr + 8) * 64 + off4];
    }

    float mrow[2] = {-1e30f, -1e30f};
    float lrow[2] = {0.0f, 0.0f};
    float o[8][4] = {};

    for (int kn0 = 0; kn0 < nv; kn0 += 64) {
        const float* Kb = g_K + (b * S_ + kn0) * D_ + h * DK_;
        const float* Vb = g_V + (b * S_ + kn0) * D_ + h * DK_;
        const bool full = (nv - kn0) >= 64;

        __syncthreads();  // prev iter's K/V/P readers done; also Q-frag reads (iter 0)
#pragma unroll
        for (int i = 0; i < 4; i++) {
            int idx = tid + i * 256;
            int r = idx >> 4, c4 = idx & 15;
            float4 kv = *(const float4*)&Kb[r * D_ + c4 * 4];
            uint4 kt = make_uint4(f2tf32(kv.x), f2tf32(kv.y), f2tf32(kv.z), f2tf32(kv.w));
            *(uint4*)&Ks[r * 64 + SW1(r, c4 * 4)] = kt;
            float4 vv = *(const float4*)&Vb[r * D_ + c4 * 4];
            uint4 vt = make_uint4(f2tf32(vv.x), f2tf32(vv.y), f2tf32(vv.z), f2tf32(vv.w));
            *(uint4*)&Vs[r * 64 + SW2(r, c4 * 4)] = vt;
        }
        __syncthreads();

        // ---- S = Q K^T ----
        float s[8][4] = {};
#pragma unroll
        for (int ks = 0; ks < 8; ks++) {
            const int off = (ks * 8 + klane) ^ (qlane << 2);
            const int off4 = off ^ 4;
#pragma unroll
            for (int nt = 0; nt < 8; nt++) {
                int brow = nt * 8 + qlane;   // row&7 == qlane
                mma_tf32(s[nt], qf[ks][0], qf[ks][1], qf[ks][2], qf[ks][3],
                         Ks[brow * 64 + off], Ks[brow * 64 + off4]);
            }
        }

        // ---- online softmax (log2 domain; tail-only masking) ----
        if (!full) {
#pragma unroll
            for (int nt = 0; nt < 8; nt++) {
                int n0 = kn0 + nt * 8 + 2 * klane;
                if (n0 >= nv) { s[nt][0] = -1e30f; s[nt][2] = -1e30f; }
                if (n0 + 1 >= nv) { s[nt][1] = -1e30f; s[nt][3] = -1e30f; }
            }
        }
        float mloc[2] = {-1e30f, -1e30f};
#pragma unroll
        for (int nt = 0; nt < 8; nt++) {
            mloc[0] = fmaxf(mloc[0], fmaxf(s[nt][0], s[nt][1]));
            mloc[1] = fmaxf(mloc[1], fmaxf(s[nt][2], s[nt][3]));
        }
#pragma unroll
        for (int i = 0; i < 2; i++) {
            mloc[i] = fmaxf(mloc[i], __shfl_xor_sync(0xffffffffu, mloc[i], 1));
            mloc[i] = fmaxf(mloc[i], __shfl_xor_sync(0xffffffffu, mloc[i], 2));
        }
        float mnew[2], alpha[2];
#pragma unroll
        for (int i = 0; i < 2; i++) {
            mnew[i] = fmaxf(mrow[i], mloc[i]);
            alpha[i] = ex2f(mrow[i] - mnew[i]);
            mrow[i] = mnew[i];
        }

        float rs[2] = {0.0f, 0.0f};
#pragma unroll
        for (int nt = 0; nt < 8; nt++) {
            int col = nt * 8 + 2 * klane;
            float p00 = ex2f(s[nt][0] - mnew[0]);
            float p01 = ex2f(s[nt][1] - mnew[0]);
            float p10 = ex2f(s[nt][2] - mnew[1]);
            float p11 = ex2f(s[nt][3] - mnew[1]);
            rs[0] += p00 + p01;
            rs[1] += p10 + p11;
            // P write: adjacent pair, 8-byte aligned (col even, swizzle keeps bits<2)
            int a0 = qr * 64 + SW1(qlane, col);
            int a1 = (qr + 8) * 64 + SW1(qlane, col);
            *(uint2*)&QsPs[a0] = make_uint2(f2tf32(p00), f2tf32(p01));
            *(uint2*)&QsPs[a1] = make_uint2(f2tf32(p10), f2tf32(p11));
        }
#pragma unroll
        for (int i = 0; i < 2; i++) {
            rs[i] += __shfl_xor_sync(0xffffffffu, rs[i], 1);
            rs[i] += __shfl_xor_sync(0xffffffffu, rs[i], 2);
            lrow[i] = lrow[i] * alpha[i] + rs[i];
        }
#pragma unroll
        for (int nt = 0; nt < 8; nt++) {
            o[nt][0] *= alpha[0]; o[nt][1] *= alpha[0];
            o[nt][2] *= alpha[1]; o[nt][3] *= alpha[1];
        }

        __syncwarp();  // P tile (warp-local rows) visible to this warp

        // ---- O += P V ----
#pragma unroll
        for (int kc = 0; kc < 8; kc++) {
            const int off = (kc * 8 + klane) ^ (qlane << 2);
            const int off4 = off ^ 4;
            unsigned a0 = QsPs[qr * 64 + off];
            unsigned a1 = QsPs[(qr + 8) * 64 + off];
            unsigned a2 = QsPs[qr * 64 + off4];
            unsigned a3 = QsPs[(qr + 8) * 64 + off4];
            const int r0 = kc * 8 + klane;       // r0&3 == klane
            const int r1 = r0 + 4;               // r1&3 == klane
#pragma unroll
            for (int nt = 0; nt < 8; nt++) {
                int vc = SW2(klane, nt * 8 + qlane);
                mma_tf32(o[nt], a0, a1, a2, a3,
                         Vs[r0 * 64 + vc], Vs[r1 * 64 + vc]);
            }
        }
        __syncwarp();  // Ps reads done before next iter's writes
    }

    // normalize + write (no valid keys -> 0, matching nan_to_num)
    float inv0 = (lrow[0] > 0.0f) ? (1.0f / lrow[0]) : 0.0f;
    float inv1 = (lrow[1] > 0.0f) ? (1.0f / lrow[1]) : 0.0f;
    float* Ob = g_AO + (b * S_ + qm0) * D_ + h * DK_;
#pragma unroll
    for (int nt = 0; nt < 8; nt++) {
        int c = nt * 8 + 2 * klane;
        *(float2*)&Ob[qr * D_ + c] = make_float2(o[nt][0] * inv0, o[nt][1] * inv0);
        *(float2*)&Ob[(qr + 8) * D_ + c] = make_float2(o[nt][2] * inv1, o[nt][3] * inv1);
    }
}

// ---------------- launch ----------------
extern "C" void kernel_launch(void* const* d_in, const int* in_sizes, int n_in,
                              void* d_out, int out_size) {
    const float* q  = (const float*)d_in[0];
    const float* k  = (const float*)d_in[1];
    const float* v  = (const float*)d_in[2];
    const int* mask = (const int*)d_in[3];
    const float* wq = (const float*)d_in[4];
    const float* wk = (const float*)d_in[5];
    const float* wv = (const float*)d_in[6];
    const float* wo = (const float*)d_in[7];
    float* out = (float*)d_out;

    compact_mask_kernel<<<B_, 1024>>>(mask);

    dim3 gproj(MROWS / 128, D_ / 128, 3);
    proj_qkv_kernel<<<gproj, 256>>>(q, k, v, wq, wk, wv);

    cudaFuncSetAttribute(flash_attn_kernel,
                         cudaFuncAttributeMaxDynamicSharedMemorySize, FSM_BYTES);
    dim3 gattn(S_ / 128, B_ * H_);
    flash_attn_kernel<<<gattn, 256, FSM_BYTES>>>();

    dim3 gout(MROWS / 128, D_ / 128);
    proj_out_kernel<<<gout, 256>>>(wo, out);
}